// round 10
// baseline (speedup 1.0000x reference)
#include <cuda_runtime.h>
#include <cstdint>

// LIF forward scan:
//   v_t = BETA * v_{t-1} * (1 - s_{t-1}) + i_t   (hard reset)
//   s_t = (v_t >= 1.0)
// Outputs: spikes (B,T,H), membrane (B,T,H), v_final (B,H) — concatenated in d_out.
//
// R10: R9 + chip-wide phase decorrelation. All blocks previously executed
// identical schedules in lockstep -> DRAM saw synchronized single-stream
// write bursts alternating with read phases (duty-cycle loss, pinned at ~71%).
// Odd blocks now (a) flush mem before spikes and (b) stagger their flush
// boundary by half a chunk, so at any instant the controller sees a steady
// read/spike/mem mix.

#define LIF_BETA 0.904837f

static constexpr int Bc = 16;
static constexpr int Tc = 1024;
static constexpr int Hc = 2048;
static constexpr int CPT = 4;                 // chains per thread
static constexpr int NT  = 64;                // threads per block (2 warps)
static constexpr int BH  = NT * CPT;          // 256 h per block
static constexpr int CHUNK  = 8;              // time steps per stage
static constexpr int HALF   = CHUNK / 2;      // stagger offset for odd blocks
static constexpr int NSTAGE = 6;              // ring depth (48KB smem)
static constexpr int NCHUNK = Tc / CHUNK;     // 128

__device__ __forceinline__ void cp_async16(uint32_t saddr, const void* gsrc) {
    asm volatile("cp.async.cg.shared.global [%0], [%1], 16;\n"
                 :: "r"(saddr), "l"(gsrc));
}
__device__ __forceinline__ void cp_commit() {
    asm volatile("cp.async.commit_group;\n");
}
template <int N>
__device__ __forceinline__ void cp_wait() {
    asm volatile("cp.async.wait_group %0;\n" :: "n"(N));
}

__global__ __launch_bounds__(NT)
void lif_kernel(const float* __restrict__ in,   // (B, T, H)
                const float* __restrict__ v0,   // (B, H)
                float* __restrict__ out)        // [spikes | membrane | v_final]
{
    __shared__ float stage[NSTAGE][CHUNK][BH];  // 6*8*256*4 = 48KB

    const int tid = threadIdx.x;
    const int chain0 = blockIdx.x * BH + tid * CPT;
    const int b  = chain0 >> 11;                      // / 2048
    const int h0 = (blockIdx.x * BH) & (Hc - 1);
    const bool odd = (blockIdx.x & 1);

    const size_t plane = (size_t)Bc * Tc * Hc;
    float* __restrict__ spikes = out;
    float* __restrict__ mem    = out + plane;
    float* __restrict__ vfin   = out + 2 * plane;

    const size_t rowbase = (size_t)b * Tc * Hc + h0;
    const int elem = tid * CPT;                       // this thread's float4 slot

    // Thread copies and later consumes exactly its own 16B segment of each
    // row -> per-thread cp.async wait_group ordering suffices, no block syncs.
    auto issue_stage = [&](int c) {
        const int st = c % NSTAGE;
        const size_t gbase = rowbase + (size_t)c * CHUNK * Hc + elem;
#pragma unroll
        for (int e = 0; e < CHUNK; ++e) {
            uint32_t saddr = (uint32_t)__cvta_generic_to_shared(&stage[st][e][elem]);
            cp_async16(saddr, in + gbase + (size_t)e * Hc);
        }
    };

#pragma unroll
    for (int c = 0; c < NSTAGE - 1; ++c) {
        issue_stage(c);
        cp_commit();
    }

    float4 vi = *(const float4*)(v0 + chain0);
    float va = vi.x, vb = vi.y, vc = vi.z, vd = vi.w;
    float sa = 0.f, sb = 0.f, sc = 0.f, sd = 0.f;

    // Pending output rows: a sliding window of up to CHUNK rows awaiting flush.
    float4 spb[CHUNK];
    float4 vmb[CHUNK];
    int npend = 0;          // rows currently staged
    int pend_t0 = 0;        // global time step of spb[0]

    // Flush the pending window as two stream-segregated bursts.
    auto flush = [&]() {
        const size_t obase = rowbase + (size_t)pend_t0 * Hc + elem;
        if (!odd) {
#pragma unroll 4
            for (int e = 0; e < npend; ++e)
                __stcs((float4*)(spikes + obase + (size_t)e * Hc), spb[e]);
#pragma unroll 4
            for (int e = 0; e < npend; ++e)
                __stcs((float4*)(mem + obase + (size_t)e * Hc), vmb[e]);
        } else {
#pragma unroll 4
            for (int e = 0; e < npend; ++e)
                __stcs((float4*)(mem + obase + (size_t)e * Hc), vmb[e]);
#pragma unroll 4
            for (int e = 0; e < npend; ++e)
                __stcs((float4*)(spikes + obase + (size_t)e * Hc), spb[e]);
        }
        pend_t0 += npend;
        npend = 0;
    };

    for (int c = 0; c < NCHUNK; ++c) {
        if (c + NSTAGE - 1 < NCHUNK)
            issue_stage(c + NSTAGE - 1);
        cp_commit();
        cp_wait<NSTAGE - 1>();

        const int st = c % NSTAGE;

#pragma unroll
        for (int e = 0; e < CHUNK; ++e) {
            const float4 x = *(const float4*)&stage[st][e][elem];
            float vr;
            vr = (sa != 0.f) ? 0.f : va;  va = fmaf(LIF_BETA, vr, x.x);  sa = (va >= 1.f) ? 1.f : 0.f;
            vr = (sb != 0.f) ? 0.f : vb;  vb = fmaf(LIF_BETA, vr, x.y);  sb = (vb >= 1.f) ? 1.f : 0.f;
            vr = (sc != 0.f) ? 0.f : vc;  vc = fmaf(LIF_BETA, vr, x.z);  sc = (vc >= 1.f) ? 1.f : 0.f;
            vr = (sd != 0.f) ? 0.f : vd;  vd = fmaf(LIF_BETA, vr, x.w);  sd = (vd >= 1.f) ? 1.f : 0.f;
            spb[npend] = make_float4(sa, sb, sc, sd);
            vmb[npend] = make_float4(va, vb, vc, vd);
            ++npend;

            // Even blocks flush at chunk boundaries (npend==CHUNK at e==7).
            // Odd blocks flush half a chunk out of phase: first flush after
            // HALF steps, then every CHUNK steps (window spans two chunks).
            if (odd && c == 0 && e == HALF - 1) flush();
            else if (npend == CHUNK) flush();
        }
    }
    if (npend) flush();   // odd blocks' trailing half chunk

    *(float4*)(vfin + chain0) = make_float4(va, vb, vc, vd);
}

extern "C" void kernel_launch(void* const* d_in, const int* in_sizes, int n_in,
                              void* d_out, int out_size)
{
    const float* input = (const float*)d_in[0];   // (16, 1024, 2048) float32
    const float* v0    = (const float*)d_in[1];   // (16, 2048) float32
    float* out         = (float*)d_out;

    const int nchains = Bc * Hc;                  // 32768
    const int grid = nchains / BH;                // 128 blocks of 2 warps
    lif_kernel<<<grid, NT>>>(input, v0, out);
}

// round 11
// speedup vs baseline: 2.5606x; 2.5606x over previous
#include <cuda_runtime.h>
#include <cstdint>

// LIF forward scan:
//   v_t = BETA * v_{t-1} * (1 - s_{t-1}) + i_t   (hard reset)
//   s_t = (v_t >= 1.0)
// Outputs: spikes (B,T,H), membrane (B,T,H), v_final (B,H) — concatenated in d_out.
//
// R11: R9 (float4 chains, 6-stage cp.async ring, 8-step stream-segregated
// flush, 2-warp blocks) + STATIC write-stream decorrelation: odd blocks flush
// mem before spikes. All staging arrays keep compile-time indices (R10's
// dynamic window spilled them to local memory -> 2.7x regression).

#define LIF_BETA 0.904837f

static constexpr int Bc = 16;
static constexpr int Tc = 1024;
static constexpr int Hc = 2048;
static constexpr int CPT = 4;                 // chains per thread
static constexpr int NT  = 64;                // threads per block (2 warps)
static constexpr int BH  = NT * CPT;          // 256 h per block
static constexpr int CHUNK  = 8;              // time steps per stage / flush batch
static constexpr int NSTAGE = 6;              // ring depth (48KB smem)
static constexpr int NCHUNK = Tc / CHUNK;     // 128

__device__ __forceinline__ void cp_async16(uint32_t saddr, const void* gsrc) {
    asm volatile("cp.async.cg.shared.global [%0], [%1], 16;\n"
                 :: "r"(saddr), "l"(gsrc));
}
__device__ __forceinline__ void cp_commit() {
    asm volatile("cp.async.commit_group;\n");
}
template <int N>
__device__ __forceinline__ void cp_wait() {
    asm volatile("cp.async.wait_group %0;\n" :: "n"(N));
}

__global__ __launch_bounds__(NT)
void lif_kernel(const float* __restrict__ in,   // (B, T, H)
                const float* __restrict__ v0,   // (B, H)
                float* __restrict__ out)        // [spikes | membrane | v_final]
{
    __shared__ float stage[NSTAGE][CHUNK][BH];  // 6*8*256*4 = 48KB

    const int tid = threadIdx.x;
    const int chain0 = blockIdx.x * BH + tid * CPT;
    const int b  = chain0 >> 11;                      // / 2048
    const int h0 = (blockIdx.x * BH) & (Hc - 1);
    const bool odd = (blockIdx.x & 1);

    const size_t plane = (size_t)Bc * Tc * Hc;
    float* __restrict__ spikes = out;
    float* __restrict__ mem    = out + plane;
    float* __restrict__ vfin   = out + 2 * plane;

    const size_t rowbase = (size_t)b * Tc * Hc + h0;
    const int elem = tid * CPT;                       // this thread's float4 slot

    // Thread copies and later consumes exactly its own 16B segment of each
    // row -> per-thread cp.async wait_group ordering suffices, no block syncs.
    auto issue_stage = [&](int c) {
        const int st = c % NSTAGE;
        const size_t gbase = rowbase + (size_t)c * CHUNK * Hc + elem;
#pragma unroll
        for (int e = 0; e < CHUNK; ++e) {
            uint32_t saddr = (uint32_t)__cvta_generic_to_shared(&stage[st][e][elem]);
            cp_async16(saddr, in + gbase + (size_t)e * Hc);
        }
    };

#pragma unroll
    for (int c = 0; c < NSTAGE - 1; ++c) {
        issue_stage(c);
        cp_commit();
    }

    float4 vi = *(const float4*)(v0 + chain0);
    float va = vi.x, vb = vi.y, vc = vi.z, vd = vi.w;
    float sa = 0.f, sb = 0.f, sc = 0.f, sd = 0.f;

    float4 spb[CHUNK];   // staged spike rows (compile-time indexed only)
    float4 vmb[CHUNK];   // staged membrane rows

    for (int c = 0; c < NCHUNK; ++c) {
        if (c + NSTAGE - 1 < NCHUNK)
            issue_stage(c + NSTAGE - 1);
        cp_commit();
        cp_wait<NSTAGE - 1>();

        const int st = c % NSTAGE;

        // Phase 1: compute CHUNK steps, outputs staged in registers.
#pragma unroll
        for (int e = 0; e < CHUNK; ++e) {
            const float4 x = *(const float4*)&stage[st][e][elem];
            float vr;
            vr = (sa != 0.f) ? 0.f : va;  va = fmaf(LIF_BETA, vr, x.x);  sa = (va >= 1.f) ? 1.f : 0.f;
            vr = (sb != 0.f) ? 0.f : vb;  vb = fmaf(LIF_BETA, vr, x.y);  sb = (vb >= 1.f) ? 1.f : 0.f;
            vr = (sc != 0.f) ? 0.f : vc;  vc = fmaf(LIF_BETA, vr, x.z);  sc = (vc >= 1.f) ? 1.f : 0.f;
            vr = (sd != 0.f) ? 0.f : vd;  vd = fmaf(LIF_BETA, vr, x.w);  sd = (vd >= 1.f) ? 1.f : 0.f;
            spb[e] = make_float4(sa, sb, sc, sd);
            vmb[e] = make_float4(va, vb, vc, vd);
        }

        const size_t obase = rowbase + (size_t)c * CHUNK * Hc + elem;

        // Phase 2/3: stream-segregated flush; odd blocks use opposite stream
        // order so the chip-wide instantaneous write mix stays 50/50.
        if (!odd) {
#pragma unroll
            for (int e = 0; e < CHUNK; ++e)
                __stcs((float4*)(spikes + obase + (size_t)e * Hc), spb[e]);
#pragma unroll
            for (int e = 0; e < CHUNK; ++e)
                __stcs((float4*)(mem + obase + (size_t)e * Hc), vmb[e]);
        } else {
#pragma unroll
            for (int e = 0; e < CHUNK; ++e)
                __stcs((float4*)(mem + obase + (size_t)e * Hc), vmb[e]);
#pragma unroll
            for (int e = 0; e < CHUNK; ++e)
                __stcs((float4*)(spikes + obase + (size_t)e * Hc), spb[e]);
        }
    }

    *(float4*)(vfin + chain0) = make_float4(va, vb, vc, vd);
}

extern "C" void kernel_launch(void* const* d_in, const int* in_sizes, int n_in,
                              void* d_out, int out_size)
{
    const float* input = (const float*)d_in[0];   // (16, 1024, 2048) float32
    const float* v0    = (const float*)d_in[1];   // (16, 2048) float32
    float* out         = (float*)d_out;

    const int nchains = Bc * Hc;                  // 32768
    const int grid = nchains / BH;                // 128 blocks of 2 warps
    lif_kernel<<<grid, NT>>>(input, v0, out);
}

// round 12
// speedup vs baseline: 2.5679x; 1.0028x over previous
#include <cuda_runtime.h>
#include <cstdint>

// LIF forward scan:
//   v_t = BETA * v_{t-1} * (1 - s_{t-1}) + i_t   (hard reset)
//   s_t = (v_t >= 1.0)
// Outputs: spikes (B,T,H), membrane (B,T,H), v_final (B,H) — concatenated in d_out.
//
// R12: R9 config (float4 chains, 6-stage cp.async ring, 8-step stream-
// segregated flush, 2-warp blocks) with inverted L2 cache policies:
//   - input reads: cp.async + L2::evict_first (dead data, free L2 fast)
//   - output writes: default .wb (dirty lines linger; L2 writes back in
//     large lazy sweeps instead of forced fine-grained R/W interleave)
// Theory: use the 126MB L2 as a write-combining buffer to cut DRAM
// read/write turnaround — the confirmed ~71%-busy plateau.

#define LIF_BETA 0.904837f

static constexpr int Bc = 16;
static constexpr int Tc = 1024;
static constexpr int Hc = 2048;
static constexpr int CPT = 4;                 // chains per thread
static constexpr int NT  = 64;                // threads per block (2 warps)
static constexpr int BH  = NT * CPT;          // 256 h per block
static constexpr int CHUNK  = 8;              // time steps per stage / flush batch
static constexpr int NSTAGE = 6;              // ring depth (48KB smem)
static constexpr int NCHUNK = Tc / CHUNK;     // 128

__device__ __forceinline__ uint64_t l2_evict_first_policy() {
    uint64_t pol;
    asm("createpolicy.fractional.L2::evict_first.b64 %0, 1.0;" : "=l"(pol));
    return pol;
}

__device__ __forceinline__ void cp_async16_ef(uint32_t saddr, const void* gsrc,
                                              uint64_t pol) {
    asm volatile("cp.async.cg.shared.global.L2::cache_hint [%0], [%1], 16, %2;\n"
                 :: "r"(saddr), "l"(gsrc), "l"(pol));
}
__device__ __forceinline__ void cp_commit() {
    asm volatile("cp.async.commit_group;\n");
}
template <int N>
__device__ __forceinline__ void cp_wait() {
    asm volatile("cp.async.wait_group %0;\n" :: "n"(N));
}

__global__ __launch_bounds__(NT)
void lif_kernel(const float* __restrict__ in,   // (B, T, H)
                const float* __restrict__ v0,   // (B, H)
                float* __restrict__ out)        // [spikes | membrane | v_final]
{
    __shared__ float stage[NSTAGE][CHUNK][BH];  // 6*8*256*4 = 48KB

    const int tid = threadIdx.x;
    const int chain0 = blockIdx.x * BH + tid * CPT;
    const int b  = chain0 >> 11;                      // / 2048
    const int h0 = (blockIdx.x * BH) & (Hc - 1);

    const size_t plane = (size_t)Bc * Tc * Hc;
    float* __restrict__ spikes = out;
    float* __restrict__ mem    = out + plane;
    float* __restrict__ vfin   = out + 2 * plane;

    const size_t rowbase = (size_t)b * Tc * Hc + h0;
    const int elem = tid * CPT;                       // this thread's float4 slot

    const uint64_t pol = l2_evict_first_policy();

    // Thread copies and later consumes exactly its own 16B segment of each
    // row -> per-thread cp.async wait_group ordering suffices, no block syncs.
    auto issue_stage = [&](int c) {
        const int st = c % NSTAGE;
        const size_t gbase = rowbase + (size_t)c * CHUNK * Hc + elem;
#pragma unroll
        for (int e = 0; e < CHUNK; ++e) {
            uint32_t saddr = (uint32_t)__cvta_generic_to_shared(&stage[st][e][elem]);
            cp_async16_ef(saddr, in + gbase + (size_t)e * Hc, pol);
        }
    };

#pragma unroll
    for (int c = 0; c < NSTAGE - 1; ++c) {
        issue_stage(c);
        cp_commit();
    }

    float4 vi = *(const float4*)(v0 + chain0);
    float va = vi.x, vb = vi.y, vc = vi.z, vd = vi.w;
    float sa = 0.f, sb = 0.f, sc = 0.f, sd = 0.f;

    float4 spb[CHUNK];   // staged spike rows (compile-time indexed only)
    float4 vmb[CHUNK];   // staged membrane rows

    for (int c = 0; c < NCHUNK; ++c) {
        if (c + NSTAGE - 1 < NCHUNK)
            issue_stage(c + NSTAGE - 1);
        cp_commit();
        cp_wait<NSTAGE - 1>();

        const int st = c % NSTAGE;

        // Phase 1: compute CHUNK steps, outputs staged in registers.
#pragma unroll
        for (int e = 0; e < CHUNK; ++e) {
            const float4 x = *(const float4*)&stage[st][e][elem];
            float vr;
            vr = (sa != 0.f) ? 0.f : va;  va = fmaf(LIF_BETA, vr, x.x);  sa = (va >= 1.f) ? 1.f : 0.f;
            vr = (sb != 0.f) ? 0.f : vb;  vb = fmaf(LIF_BETA, vr, x.y);  sb = (vb >= 1.f) ? 1.f : 0.f;
            vr = (sc != 0.f) ? 0.f : vc;  vc = fmaf(LIF_BETA, vr, x.z);  sc = (vc >= 1.f) ? 1.f : 0.f;
            vr = (sd != 0.f) ? 0.f : vd;  vd = fmaf(LIF_BETA, vr, x.w);  sd = (vd >= 1.f) ? 1.f : 0.f;
            spb[e] = make_float4(sa, sb, sc, sd);
            vmb[e] = make_float4(va, vb, vc, vd);
        }

        const size_t obase = rowbase + (size_t)c * CHUNK * Hc + elem;

        // Phase 2: flush spike stream (default .wb stores — L2 buffers them).
#pragma unroll
        for (int e = 0; e < CHUNK; ++e)
            *(float4*)(spikes + obase + (size_t)e * Hc) = spb[e];

        // Phase 3: flush membrane stream.
#pragma unroll
        for (int e = 0; e < CHUNK; ++e)
            *(float4*)(mem + obase + (size_t)e * Hc) = vmb[e];
    }

    *(float4*)(vfin + chain0) = make_float4(va, vb, vc, vd);
}

extern "C" void kernel_launch(void* const* d_in, const int* in_sizes, int n_in,
                              void* d_out, int out_size)
{
    const float* input = (const float*)d_in[0];   // (16, 1024, 2048) float32
    const float* v0    = (const float*)d_in[1];   // (16, 2048) float32
    float* out         = (float*)d_out;

    const int nchains = Bc * Hc;                  // 32768
    const int grid = nchains / BH;                // 128 blocks of 2 warps
    lif_kernel<<<grid, NT>>>(input, v0, out);
}